// round 16
// baseline (speedup 1.0000x reference)
#include <cuda_runtime.h>
#include <cuda_fp16.h>
#include <cstdint>

// SpatialDeformer3D: trilinear warp of X[...,0] by per-voxel deformation.
// Shapes fixed: B=2, H=160, W=192, D=160.
//
// R16: quad pipeline (R15) fused into ONE kernel with bid-INTERLEAVED
// producer/consumer overlap:
//   seg0 bids [0,3840):      pre batch-0 (quad panel build)
//   seg1 bids [3840,17280):  ratio-2:5 interleave of pre batch-1 : main batch-0
//   seg2 bids [17280,26880): main batch-1
// Waiters' producers all have lower bids -> resident-or-done first (classic
// launch dispatches in bid order) -> deadlock-free. Pre-b1 DRAM work hides
// under main-b0 L1-bound sampling. (R14's fusion failed because pre bids all
// preceded main bids -> zero possible overlap; this fixes the layout.)

namespace {
constexpr int B  = 2;
constexpr int H  = 160;
constexpr int W  = 192;
constexpr int D  = 160;
constexpr int WD = W * D;                 // 30720
constexpr int N  = H * W * D;             // 4,915,200 per batch
constexpr int NT = B * N;                 // 9,830,400
constexpr int THREADS = 256;

constexpr int XP = 8;                     // x-rows per pre block
constexpr int PANELS = W / XP;            // 24
constexpr int ROW_F4 = D * 2 * 4 / 16;    // 80 float4 per x-row of X
constexpr int PRE_PER_B  = H * PANELS;    // 3840
constexpr int MAIN_PER_B = (N / 2) / THREADS;  // 9600
constexpr int SEG1 = PRE_PER_B + MAIN_PER_B;   // 13440 (= 1920 * 7)
constexpr int GRID = 2 * (PRE_PER_B + MAIN_PER_B);  // 26880
}

// Quad volume: 8 B per voxel = 78.6 MB. Static scratch (no allocs allowed).
__device__ uint2 g_quad[NT];
__device__ int   g_done[2];

__global__ void init_kernel() { g_done[0] = 0; g_done[1] = 0; }

// ---------------------------------------------------------------------------
__device__ __forceinline__ float clampi_f(int v, int hi, int* out_i) {
    int c = v < 0 ? 0 : (v > hi ? hi : v);
    *out_i = c;
    return (float)c;
}

__device__ __forceinline__ float sample_one(int bN, int ix, int iy, int iz,
                                            float dx, float dy, float dz) {
    float x = (float)ix + dx;
    float y = (float)iy + dy;
    float z = (float)iz + dz;

    int x0i = (int)floorf(x);
    int y0i = (int)floorf(y);
    int z0i = (int)floorf(z);

    int y0, y1;
    float y0f = clampi_f(y0i,     H - 1, &y0);
    float y1f = clampi_f(y0i + 1, H - 1, &y1);
    float wy0 = y - y0f, wy1 = y1f - y;

    // x/z degenerate (floor outside [0,dim-2]) -> exact zero contribution
    // in the reference (w0+w1 = clip(hi)-clip(lo) = 0).
    bool xok  = (x0i >= 0) && (x0i < W - 1);
    int  xc   = xok ? x0i : 0;
    float wx0 = xok ? (x - (float)x0i)        : 0.0f;
    float wx1 = xok ? ((float)x0i + 1.0f - x) : 0.0f;

    bool zok  = (z0i >= 0) && (z0i < D - 1);
    int  zc   = zok ? z0i : 0;
    float wz0 = zok ? (z - (float)z0i)        : 0.0f;
    float wz1 = zok ? ((float)z0i + 1.0f - z) : 0.0f;

    int base = bN + xc * D + zc;
    uint2 q0 = __ldg(&g_quad[base + y0 * WD]);
    uint2 q1 = __ldg(&g_quad[base + y1 * WD]);

    __half2 lo0 = *reinterpret_cast<__half2*>(&q0.x);
    __half2 hi0 = *reinterpret_cast<__half2*>(&q0.y);
    __half2 lo1 = *reinterpret_cast<__half2*>(&q1.x);
    __half2 hi1 = *reinterpret_cast<__half2*>(&q1.y);

    float c00 = wz1 * __half2float(lo0.x) + wz0 * __half2float(lo0.y);
    float c01 = wz1 * __half2float(hi0.x) + wz0 * __half2float(hi0.y);
    float c10 = wz1 * __half2float(lo1.x) + wz0 * __half2float(lo1.y);
    float c11 = wz1 * __half2float(hi1.x) + wz0 * __half2float(hi1.y);

    float c0 = wx1 * c00 + wx0 * c01;
    float c1 = wx1 * c10 + wx0 * c11;

    return wy1 * c0 + wy0 * c1;
}

// ---------------------------------------------------------------------------
__global__ void __launch_bounds__(THREADS)
fused_kernel(const float4* __restrict__ X4,
             const float2* __restrict__ def2,
             float2* __restrict__ out2) {
    __shared__ float rows[XP + 1][D + 1];   // pre path only (5.8 KB)

    int bid = blockIdx.x;
    int tid = threadIdx.x;

    int pre_idx = -1, main_idx = -1;
    if (bid < PRE_PER_B) {
        pre_idx = bid;                                   // pre batch 0
    } else if (bid < PRE_PER_B + SEG1) {
        int k = bid - PRE_PER_B;
        int g = k / 7, m = k % 7;
        if (m < 2) pre_idx  = PRE_PER_B + g * 2 + m;     // pre batch 1
        else       main_idx = g * 5 + (m - 2);           // main batch 0
    } else {
        main_idx = MAIN_PER_B + (bid - PRE_PER_B - SEG1); // main batch 1
    }

    if (pre_idx >= 0) {
        // ---------------- Pre: build quads for 8 x-rows of one (b,y) plane --
        int p  = pre_idx % PANELS;
        int y  = (pre_idx / PANELS) % H;
        int b  = pre_idx / (PANELS * H);
        int x0 = p * XP;

        int plane_base = (b * H + y) * W;
        for (int t = tid; t < (XP + 1) * ROW_F4; t += THREADS) {
            int r = t / ROW_F4;
            int c = t - r * ROW_F4;
            int xr = x0 + r; if (xr > W - 1) xr = W - 1;
            float4 v = X4[(size_t)(plane_base + xr) * ROW_F4 + c];
            rows[r][2 * c]     = v.x;
            rows[r][2 * c + 1] = v.z;
        }
        __syncthreads();
        if (tid < XP + 1)
            rows[tid][D] = rows[tid][D - 1];   // z pad (never read)
        __syncthreads();

        uint2* dst = &g_quad[(size_t)(plane_base + x0) * D];
        for (int q = tid; q < XP * D; q += THREADS) {
            int xr = q / D;
            int z  = q - xr * D;
            __half2 lo = __floats2half2_rn(rows[xr][z],     rows[xr][z + 1]);
            __half2 hi = __floats2half2_rn(rows[xr + 1][z], rows[xr + 1][z + 1]);
            uint2 val;
            val.x = *reinterpret_cast<uint32_t*>(&lo);
            val.y = *reinterpret_cast<uint32_t*>(&hi);
            dst[q] = val;
        }

        __syncthreads();
        if (tid == 0) {
            int* ctr = &g_done[b];
            asm volatile("red.release.gpu.global.add.s32 [%0], 1;"
                         :: "l"(ctr) : "memory");
        }
        return;
    }

    // -------------------- Main: trilinear sampling -------------------------
    int j = main_idx;                       // [0, 19200)
    int b = (j < MAIN_PER_B) ? 0 : 1;

    if (tid == 0) {
        const int* ctr = &g_done[b];
        int v;
        do {
            asm volatile("ld.acquire.gpu.global.s32 %0, [%1];"
                         : "=r"(v) : "l"(ctr) : "memory");
            if (v < PRE_PER_B) __nanosleep(128);
        } while (v < PRE_PER_B);
    }
    __syncthreads();

    int t   = j * THREADS + tid;            // pair index [0, NT/2)
    int r2  = t * 2;
    int r   = r2 - b * N;
    int iy  = r / WD;
    int rem = r - iy * WD;
    int ix  = rem / D;
    int iz  = rem - ix * D;                 // even; iz+1 < D

    float2 d0 = __ldcs(&def2[3 * t + 0]);   // (dxA, dyA)
    float2 d1 = __ldcs(&def2[3 * t + 1]);   // (dzA, dxB)
    float2 d2 = __ldcs(&def2[3 * t + 2]);   // (dyB, dzB)

    int bN = b * N;
    float2 o;
    o.x = sample_one(bN, ix, iy, iz,     d0.x, d0.y, d1.x);
    o.y = sample_one(bN, ix, iy, iz + 1, d1.y, d2.x, d2.y);

    __stcs(&out2[t], o);
}

extern "C" void kernel_launch(void* const* d_in, const int* in_sizes, int n_in,
                              void* d_out, int out_size) {
    const float* X   = (const float*)d_in[0];
    const float* def = (const float*)d_in[1];

    init_kernel<<<1, 1>>>();
    fused_kernel<<<GRID, THREADS>>>(
        reinterpret_cast<const float4*>(X),
        reinterpret_cast<const float2*>(def),
        reinterpret_cast<float2*>(d_out));
}